// round 6
// baseline (speedup 1.0000x reference)
#include <cuda_runtime.h>

#define T_LEN   2048
#define BATCH   16
#define NFREQ   1152
#define NOCT    9
#define NF0     128

typedef unsigned long long u64;

// -------- device scratch --------
__device__ float g_mag[BATCH * NFREQ];
__device__ int   g_cnt[BATCH];            // zero-init; self-resetting each launch

// -------- packed f32x2 helpers --------
__device__ __forceinline__ u64 pk(float lo, float hi) {
    u64 r; asm("mov.b64 %0,{%1,%2};" : "=l"(r) : "f"(lo), "f"(hi)); return r;
}
__device__ __forceinline__ void upk(u64 v, float& lo, float& hi) {
    asm("mov.b64 {%0,%1},%2;" : "=f"(lo), "=f"(hi) : "l"(v));
}
__device__ __forceinline__ u64 bc2(float v) {       // compile-time broadcast imm
    unsigned u = __float_as_uint(v);
    return (u64)u | ((u64)u << 32);
}
__device__ __forceinline__ u64 fma2(u64 a, u64 b, u64 c) {
    u64 d; asm("fma.rn.f32x2 %0,%1,%2,%3;" : "=l"(d) : "l"(a), "l"(b), "l"(c)); return d;
}
__device__ __forceinline__ u64 mul2(u64 a, u64 b) {
    u64 d; asm("mul.rn.f32x2 %0,%1,%2;" : "=l"(d) : "l"(a), "l"(b)); return d;
}
__device__ __forceinline__ u64 add2(u64 a, u64 b) {
    u64 d; asm("add.rn.f32x2 %0,%1,%2;" : "=l"(d) : "l"(a), "l"(b)); return d;
}
__device__ __forceinline__ u64 sub2(u64 a, u64 b) {
    u64 d; asm("sub.rn.f32x2 %0,%1,%2;" : "=l"(d) : "l"(a), "l"(b)); return d;
}

// one packed pair of time steps across 9 octaves (yn preloaded/normalized)
#define EVAL_PAIR(tv, yn)                                                   \
    do {                                                                    \
        u64 x  = mul2((tv), W0);                                            \
        u64 qm = fma2(x, IPI, MAGC);                                        \
        u64 qf = sub2(qm, MAGC);                                            \
        u64 r  = fma2(qf, NPI, x);                                          \
        u64 z = mul2(r, r);                                                 \
        u64 ps = fma2(S9c, z, S7c);                                         \
        ps = fma2(ps, z, S5c);                                              \
        ps = fma2(ps, z, S3c);                                              \
        u64 s = fma2(mul2(ps, z), r, r);                                    \
        u64 pc = fma2(C10c, z, C8c);                                        \
        pc = fma2(pc, z, C6c);                                              \
        pc = fma2(pc, z, C4c);                                              \
        pc = fma2(pc, z, C2c);                                              \
        u64 c = fma2(pc, z, ONE);                                           \
        u64 ysg = (yn) ^ ((qm & 0x0000000100000001ull) << 31);              \
        A1[0] = fma2(ysg, s, A1[0]);                                        \
        A2[0] = fma2(ysg, c, A2[0]);                                        \
        _Pragma("unroll")                                                   \
        for (int k = 1; k < NOCT; k++) {                                    \
            u64 tc = add2(c, c);                                            \
            s = mul2(tc, s);            /* sin2 = 2c*s   */                 \
            c = fma2(tc, c, NEG1);      /* cos2 = 2c*c-1 */                 \
            A1[k] = fma2((yn), s, A1[k]);                                   \
            A2[k] = fma2((yn), c, A2[k]);                                   \
        }                                                                   \
    } while (0)

// -------- single fused kernel --------
// block (f0, b): 64 threads = 2 warps, 16 packed time-pairs per thread.
__global__ __launch_bounds__(64, 16) void spectral_kernel(const float* __restrict__ batch,
                                                          const float* __restrict__ freqs,
                                                          float* __restrict__ out) {
    const int f0  = blockIdx.x;
    const int b   = blockIdx.y;
    const int tid = threadIdx.x;
    const int lane = tid & 31, w = tid >> 5;

    __shared__ u64   yn_s[T_LEN / 2];        // 8 KB: packed normalized y
    __shared__ float sred[2][18];
    __shared__ float rstat[2][2];
    __shared__ float fmean_s, finv_s;
    __shared__ int   last_s;

    const float4* __restrict__ ts4 = (const float4*)(batch + b * (2 * T_LEN));
    const float4* __restrict__ ys4 = (const float4*)(batch + b * (2 * T_LEN) + T_LEN);

    // ---- prelude: per-block stats of y + stage packed yn in smem ----
    {
        u64 yv[16];
        u64 s1 = 0, sq = 0;
#pragma unroll
        for (int i = 0; i < 8; i++) {
            float4 y4 = __ldg(&ys4[i * 64 + tid]);
            yv[2 * i]     = pk(y4.x, y4.y);
            yv[2 * i + 1] = pk(y4.z, y4.w);
            s1 = add2(s1, add2(yv[2 * i], yv[2 * i + 1]));
            sq = fma2(yv[2 * i], yv[2 * i], sq);
            sq = fma2(yv[2 * i + 1], yv[2 * i + 1], sq);
        }
        float lo, hi;
        upk(s1, lo, hi); float su = lo + hi;
        upk(sq, lo, hi); float qu = lo + hi;
#pragma unroll
        for (int o = 16; o; o >>= 1) {
            su += __shfl_down_sync(0xffffffffu, su, o);
            qu += __shfl_down_sync(0xffffffffu, qu, o);
        }
        if (lane == 0) { rstat[w][0] = su; rstat[w][1] = qu; }
        __syncthreads();
        const float Sy  = rstat[0][0] + rstat[1][0];
        const float Syy = rstat[0][1] + rstat[1][1];
        const float mean = Sy * (1.0f / T_LEN);
        const float var  = (Syy - (float)T_LEN * mean * mean) * (1.0f / (T_LEN - 1));
        const float inv  = 1.0f / (sqrtf(var) + 1e-4f);
        const u64 INVb = pk(inv, inv);
        const u64 NMb  = pk(-mean * inv, -mean * inv);
#pragma unroll
        for (int i = 0; i < 16; i++)
            yn_s[i + 16 * tid] = fma2(yv[i], INVb, NMb);
        // note: thread-local contiguous layout; main loop indexes the same way
    }
    __syncthreads();

    const float w0f = freqs[f0] * 6.283185307179586f;
    const u64 W0   = pk(w0f, w0f);
    const u64 IPI  = bc2(0.3183098861837907f);
    const u64 MAGC = bc2(12582912.0f);
    const u64 NPI  = bc2(-3.14159274101257324f);   // fp32 pi, single-term CW
    const u64 S9c  = bc2( 2.7557319223985893e-6f);
    const u64 S7c  = bc2(-1.9841269841269841e-4f);
    const u64 S5c  = bc2( 8.3333333333333333e-3f);
    const u64 S3c  = bc2(-1.6666666666666666e-1f);
    const u64 C10c = bc2(-2.7557319223985893e-7f);
    const u64 C8c  = bc2( 2.4801587301587302e-5f);
    const u64 C6c  = bc2(-1.3888888888888889e-3f);
    const u64 C4c  = bc2( 4.1666666666666666e-2f);
    const u64 C2c  = bc2(-0.5f);
    const u64 ONE  = bc2(1.0f);
    const u64 NEG1 = bc2(-1.0f);

    u64 A1[NOCT], A2[NOCT];
#pragma unroll
    for (int k = 0; k < NOCT; k++) { A1[k] = 0; A2[k] = 0; }

    // ---- main loop: 8 float4 iterations = 16 packed pairs ----
#pragma unroll 2
    for (int i = 0; i < 8; i++) {
        float4 t4 = __ldg(&ts4[i * 64 + tid]);
        u64 ynA = yn_s[2 * i + 16 * tid];
        u64 ynB = yn_s[2 * i + 1 + 16 * tid];
        u64 tvA = pk(t4.x, t4.y);
        u64 tvB = pk(t4.z, t4.w);
        EVAL_PAIR(tvA, ynA);
        EVAL_PAIR(tvB, ynB);
    }

    // ---- per-warp packed butterfly reduction ----
#pragma unroll
    for (int k = 0; k < NOCT; k++) {
#pragma unroll
        for (int o = 16; o; o >>= 1) {
            A1[k] = add2(A1[k], __shfl_down_sync(0xffffffffu, A1[k], o));
            A2[k] = add2(A2[k], __shfl_down_sync(0xffffffffu, A2[k], o));
        }
    }
    if (lane == 0) {
#pragma unroll
        for (int k = 0; k < NOCT; k++) {
            float lo, hi;
            upk(A1[k], lo, hi); sred[w][k]        = lo + hi;
            upk(A2[k], lo, hi); sred[w][NOCT + k] = lo + hi;
        }
    }
    __syncthreads();

    // ---- combine 2 warps, write magnitude ----
    if (tid < NOCT) {
        float P1 = sred[0][tid]        + sred[1][tid];
        float P2 = sred[0][NOCT + tid] + sred[1][NOCT + tid];
        float m = sqrtf(fmaf(P1, P1, P2 * P2));
        __stcg(&g_mag[b * NFREQ + tid * NF0 + f0], m);
    }
    __threadfence();
    __syncthreads();
    if (tid == 0) last_s = (atomicAdd(&g_cnt[b], 1) == NF0 - 1);
    __syncthreads();
    if (!last_s) return;
    __threadfence();

    // ---- last block per batch: tnorm over 1152 freqs ----
    float mv[18];
    float sm = 0.0f, sq2 = 0.0f;
#pragma unroll
    for (int j = 0; j < 18; j++) {
        float m = __ldcg(&g_mag[b * NFREQ + j * 64 + tid]);
        mv[j] = m;
        sm += m;
        sq2 = fmaf(m, m, sq2);
    }
#pragma unroll
    for (int o = 16; o; o >>= 1) {
        sm  += __shfl_down_sync(0xffffffffu, sm, o);
        sq2 += __shfl_down_sync(0xffffffffu, sq2, o);
    }
    if (lane == 0) { rstat[w][0] = sm; rstat[w][1] = sq2; }
    __syncthreads();
    if (tid == 0) {
        float S = rstat[0][0] + rstat[1][0];
        float Q = rstat[0][1] + rstat[1][1];
        float mean = S * (1.0f / NFREQ);
        float var  = (Q - (float)NFREQ * mean * mean) * (1.0f / (NFREQ - 1));
        fmean_s = mean;
        finv_s  = 1.0f / (sqrtf(var) + 1e-4f);
        g_cnt[b] = 0;   // reset for next graph replay
    }
    __syncthreads();
    const float mmean = fmean_s, minv = finv_s;
#pragma unroll
    for (int j = 0; j < 18; j++)
        out[b * NFREQ + j * 64 + tid] = (mv[j] - mmean) * minv;
}

// -------- launch --------
extern "C" void kernel_launch(void* const* d_in, const int* in_sizes, int n_in,
                              void* d_out, int out_size) {
    const float* batch = (const float*)d_in[0];   // (16, 2, 2048) f32
    const float* freqs = (const float*)d_in[1];   // (1152,) f32
    float* out = (float*)d_out;                   // (16, 1, 1152) f32

    spectral_kernel<<<dim3(NF0, BATCH), 64>>>(batch, freqs, out);
}

// round 7
// speedup vs baseline: 1.3270x; 1.3270x over previous
#include <cuda_runtime.h>

#define T_LEN   2048
#define BATCH   16
#define NFREQ   1152
#define NOCT    9
#define NF0     128

typedef unsigned long long u64;

// -------- device scratch --------
__device__ float g_mag[BATCH * NFREQ];
__device__ int   g_cnt[BATCH];            // zero-init; self-resetting each launch

// -------- packed f32x2 helpers --------
__device__ __forceinline__ u64 pk(float lo, float hi) {
    u64 r; asm("mov.b64 %0,{%1,%2};" : "=l"(r) : "f"(lo), "f"(hi)); return r;
}
__device__ __forceinline__ void upk(u64 v, float& lo, float& hi) {
    asm("mov.b64 {%0,%1},%2;" : "=f"(lo), "=f"(hi) : "l"(v));
}
__device__ __forceinline__ u64 bc2(float v) {       // compile-time broadcast imm
    unsigned u = __float_as_uint(v);
    return (u64)u | ((u64)u << 32);
}
__device__ __forceinline__ u64 fma2(u64 a, u64 b, u64 c) {
    u64 d; asm("fma.rn.f32x2 %0,%1,%2,%3;" : "=l"(d) : "l"(a), "l"(b), "l"(c)); return d;
}
__device__ __forceinline__ u64 mul2(u64 a, u64 b) {
    u64 d; asm("mul.rn.f32x2 %0,%1,%2;" : "=l"(d) : "l"(a), "l"(b)); return d;
}
__device__ __forceinline__ u64 add2(u64 a, u64 b) {
    u64 d; asm("add.rn.f32x2 %0,%1,%2;" : "=l"(d) : "l"(a), "l"(b)); return d;
}
__device__ __forceinline__ u64 sub2(u64 a, u64 b) {
    u64 d; asm("sub.rn.f32x2 %0,%1,%2;" : "=l"(d) : "l"(a), "l"(b)); return d;
}

// one packed pair of time steps across 9 octaves.
// yn is mean-removed y (NOT std-scaled: uniform scale cancels in the final tnorm;
// the EPS perturbation this introduces is ~3e-7 relative, far below budget).
#define EVAL_PAIR(tv, yn)                                                   \
    do {                                                                    \
        u64 x  = mul2((tv), W0);                                            \
        u64 qm = fma2(x, IPI, MAGC);                                        \
        u64 qf = sub2(qm, MAGC);                                            \
        u64 r  = fma2(qf, NPI, x);                                          \
        u64 z = mul2(r, r);                                                 \
        u64 ps = fma2(S9c, z, S7c);                                         \
        ps = fma2(ps, z, S5c);                                              \
        ps = fma2(ps, z, S3c);                                              \
        u64 s = fma2(mul2(ps, z), r, r);                                    \
        u64 pc = fma2(C10c, z, C8c);                                        \
        pc = fma2(pc, z, C6c);                                              \
        pc = fma2(pc, z, C4c);                                              \
        pc = fma2(pc, z, C2c);                                              \
        u64 c = fma2(pc, z, ONE);                                           \
        u64 ysg = (yn) ^ ((qm & 0x0000000100000001ull) << 31);              \
        A1[0] = fma2(ysg, s, A1[0]);                                        \
        A2[0] = fma2(ysg, c, A2[0]);                                        \
        _Pragma("unroll")                                                   \
        for (int k = 1; k < NOCT; k++) {                                    \
            u64 tc = add2(c, c);                                            \
            s = mul2(tc, s);            /* sin2 = 2c*s   */                 \
            c = fma2(tc, c, NEG1);      /* cos2 = 2c*c-1 */                 \
            A1[k] = fma2((yn), s, A1[k]);                                   \
            A2[k] = fma2((yn), c, A2[k]);                                   \
        }                                                                   \
    } while (0)

// -------- single fused kernel --------
// block (f0, b): 64 threads = 2 warps, 16 packed time-pairs per thread.
__global__ __launch_bounds__(64) void spectral_kernel(const float* __restrict__ batch,
                                                      const float* __restrict__ freqs,
                                                      float* __restrict__ out) {
    const int f0  = blockIdx.x;
    const int b   = blockIdx.y;
    const int tid = threadIdx.x;
    const int lane = tid & 31, w = tid >> 5;

    __shared__ float sred[2][18];
    __shared__ float rstat[2][2];
    __shared__ float fmean_s, finv_s;
    __shared__ int   last_s;

    const float4* __restrict__ ts4 = (const float4*)(batch + b * (2 * T_LEN));
    const float4* __restrict__ ys4 = (const float4*)(batch + b * (2 * T_LEN) + T_LEN);

    // ---- slim prelude: block-redundant mean of y (sum only) ----
    float msum = 0.0f;
#pragma unroll
    for (int i = 0; i < 8; i++) {
        float4 v = __ldg(&ys4[i * 64 + tid]);
        msum += (v.x + v.y) + (v.z + v.w);
    }
#pragma unroll
    for (int o = 16; o; o >>= 1) msum += __shfl_down_sync(0xffffffffu, msum, o);
    if (lane == 0) rstat[w][0] = msum;
    __syncthreads();
    const float m = (rstat[0][0] + rstat[1][0]) * (1.0f / T_LEN);
    const u64 M = pk(m, m);

    const float w0f = freqs[f0] * 6.283185307179586f;
    const u64 W0   = pk(w0f, w0f);
    const u64 IPI  = bc2(0.3183098861837907f);
    const u64 MAGC = bc2(12582912.0f);
    const u64 NPI  = bc2(-3.14159274101257324f);   // fp32 pi, single-term CW
    const u64 S9c  = bc2( 2.7557319223985893e-6f);
    const u64 S7c  = bc2(-1.9841269841269841e-4f);
    const u64 S5c  = bc2( 8.3333333333333333e-3f);
    const u64 S3c  = bc2(-1.6666666666666666e-1f);
    const u64 C10c = bc2(-2.7557319223985893e-7f);
    const u64 C8c  = bc2( 2.4801587301587302e-5f);
    const u64 C6c  = bc2(-1.3888888888888889e-3f);
    const u64 C4c  = bc2( 4.1666666666666666e-2f);
    const u64 C2c  = bc2(-0.5f);
    const u64 ONE  = bc2(1.0f);
    const u64 NEG1 = bc2(-1.0f);

    u64 A1[NOCT], A2[NOCT];
#pragma unroll
    for (int k = 0; k < NOCT; k++) { A1[k] = 0; A2[k] = 0; }

    // ---- main loop: software-pipelined (1 iter lookahead) ----
    float4 t_n = __ldg(&ts4[tid]);
    float4 y_n = __ldg(&ys4[tid]);
#pragma unroll
    for (int i = 0; i < 8; i++) {
        float4 t4 = t_n, y4 = y_n;
        if (i < 7) {
            t_n = __ldg(&ts4[(i + 1) * 64 + tid]);
            y_n = __ldg(&ys4[(i + 1) * 64 + tid]);
        }
        u64 tvA = pk(t4.x, t4.y), ynA = sub2(pk(y4.x, y4.y), M);
        u64 tvB = pk(t4.z, t4.w), ynB = sub2(pk(y4.z, y4.w), M);
        EVAL_PAIR(tvA, ynA);
        EVAL_PAIR(tvB, ynB);
    }

    // ---- per-warp packed butterfly reduction ----
#pragma unroll
    for (int k = 0; k < NOCT; k++) {
#pragma unroll
        for (int o = 16; o; o >>= 1) {
            A1[k] = add2(A1[k], __shfl_down_sync(0xffffffffu, A1[k], o));
            A2[k] = add2(A2[k], __shfl_down_sync(0xffffffffu, A2[k], o));
        }
    }
    if (lane == 0) {
#pragma unroll
        for (int k = 0; k < NOCT; k++) {
            float lo, hi;
            upk(A1[k], lo, hi); sred[w][k]        = lo + hi;
            upk(A2[k], lo, hi); sred[w][NOCT + k] = lo + hi;
        }
    }
    __syncthreads();

    // ---- combine 2 warps, write magnitude (scale of yn deliberately omitted) ----
    if (tid < NOCT) {
        float P1 = sred[0][tid]        + sred[1][tid];
        float P2 = sred[0][NOCT + tid] + sred[1][NOCT + tid];
        float mg = sqrtf(fmaf(P1, P1, P2 * P2));
        __stcg(&g_mag[b * NFREQ + tid * NF0 + f0], mg);
    }
    __threadfence();
    __syncthreads();
    if (tid == 0) last_s = (atomicAdd(&g_cnt[b], 1) == NF0 - 1);
    __syncthreads();
    if (!last_s) return;
    __threadfence();

    // ---- last block per batch: tnorm over 1152 freqs ----
    float mv[18];
    float sm = 0.0f, sq2 = 0.0f;
#pragma unroll
    for (int j = 0; j < 18; j++) {
        float v = __ldcg(&g_mag[b * NFREQ + j * 64 + tid]);
        mv[j] = v;
        sm += v;
        sq2 = fmaf(v, v, sq2);
    }
#pragma unroll
    for (int o = 16; o; o >>= 1) {
        sm  += __shfl_down_sync(0xffffffffu, sm, o);
        sq2 += __shfl_down_sync(0xffffffffu, sq2, o);
    }
    if (lane == 0) { rstat[w][0] = sm; rstat[w][1] = sq2; }
    __syncthreads();
    if (tid == 0) {
        float S = rstat[0][0] + rstat[1][0];
        float Q = rstat[0][1] + rstat[1][1];
        float mean = S * (1.0f / NFREQ);
        float var  = (Q - (float)NFREQ * mean * mean) * (1.0f / (NFREQ - 1));
        fmean_s = mean;
        finv_s  = 1.0f / (sqrtf(var) + 1e-4f);
        g_cnt[b] = 0;   // reset for next graph replay
    }
    __syncthreads();
    const float mmean = fmean_s, minv = finv_s;
#pragma unroll
    for (int j = 0; j < 18; j++)
        out[b * NFREQ + j * 64 + tid] = (mv[j] - mmean) * minv;
}

// -------- launch --------
extern "C" void kernel_launch(void* const* d_in, const int* in_sizes, int n_in,
                              void* d_out, int out_size) {
    const float* batch = (const float*)d_in[0];   // (16, 2, 2048) f32
    const float* freqs = (const float*)d_in[1];   // (1152,) f32
    float* out = (float*)d_out;                   // (16, 1, 1152) f32

    spectral_kernel<<<dim3(NF0, BATCH), 64>>>(batch, freqs, out);
}